// round 1
// baseline (speedup 1.0000x reference)
#include <cuda_runtime.h>

// Equivariant linear: segments (u,i) = (64,1),(32,3),(16,5); in==out dim 240.
// out[n, seg_off + v*i + ii] = (1/sqrt(u)) * sum_u x[n, seg_off + u*i + ii] * w[u][v]

typedef unsigned long long u64;

__device__ __forceinline__ u64 fma2(u64 a, u64 b, u64 c) {
    u64 d;
    asm("fma.rn.f32x2 %0, %1, %2, %3;" : "=l"(d) : "l"(a), "l"(b), "l"(c));
    return d;
}
__device__ __forceinline__ u64 dup2(float x) {
    u64 d;
    asm("mov.b64 %0, {%1, %2};" : "=l"(d) : "f"(x), "f"(x));
    return d;
}
__device__ __forceinline__ u64 pack2(float x, float y) {
    u64 d;
    asm("mov.b64 %0, {%1, %2};" : "=l"(d) : "f"(x), "f"(y));
    return d;
}
__device__ __forceinline__ void unpack2(u64 v, float& a, float& b) {
    asm("mov.b64 {%0, %1}, %2;" : "=f"(a), "=f"(b) : "l"(v));
}

__global__ __launch_bounds__(128) void eqlin_kernel(
    const float* __restrict__ x,
    const float* __restrict__ w,
    float* __restrict__ out,
    int n)
{
    __shared__ __align__(16) float sw[5376];  // pre-scaled weights

    const int tid = threadIdx.x;

    // Load + scale weights: w1 *= 1/8, w2 *= 1/sqrt(32), w3 *= 1/4
    #pragma unroll
    for (int k = 0; k < 42; k++) {
        int idx = tid + k * 128;  // 42*128 = 5376 exactly
        float s = (idx < 4096) ? 0.125f
                 : (idx < 5120) ? 0.17677669529663687f
                                : 0.25f;
        sw[idx] = w[idx] * s;
    }
    __syncthreads();

    const int ty = tid >> 4;       // 0..7  -> 4 rows each
    const int tx = tid & 15;       // 0..15 -> output-column slice

    const int r0 = blockIdx.x * 32 + ty * 4;
    // clamp row indices for loads (tail-safe); stores are predicated
    int rr[4];
    bool wr[4];
    #pragma unroll
    for (int s = 0; s < 4; s++) {
        int r = r0 + s;
        wr[s] = (r < n);
        rr[s] = wr[s] ? r : (n - 1);
    }
    const float* xr[4];
    float* orw[4];
    #pragma unroll
    for (int s = 0; s < 4; s++) {
        xr[s]  = x   + (long long)rr[s] * 240;
        orw[s] = out + (long long)rr[s] * 240;
    }

    // ------------------------------------------------------------------
    // Segment 1: u=v=64, i=1.  cols 0..63.  thread covers v0=4*tx..+3.
    // v-pair packing: acc2 = (out[v], out[v+1]); w pairs via ulonglong2.
    // ------------------------------------------------------------------
    {
        const ulonglong2* w1p = (const ulonglong2*)sw;  // pair-pair index: (u*64+4tx)/4 = u*16+tx
        u64 acc[4][2];
        #pragma unroll
        for (int s = 0; s < 4; s++) { acc[s][0] = 0ull; acc[s][1] = 0ull; }

        #pragma unroll 4
        for (int k = 0; k < 16; k++) {          // u = 4k .. 4k+3
            float4 xv[4];
            #pragma unroll
            for (int s = 0; s < 4; s++)
                xv[s] = *(const float4*)(xr[s] + 4 * k);
            #pragma unroll
            for (int uu = 0; uu < 4; uu++) {
                const int u = 4 * k + uu;
                ulonglong2 wp = w1p[u * 16 + tx];   // (w[u][4tx..4tx+3]) as two f32x2
                #pragma unroll
                for (int s = 0; s < 4; s++) {
                    float xs = (uu == 0) ? xv[s].x : (uu == 1) ? xv[s].y
                             : (uu == 2) ? xv[s].z : xv[s].w;
                    u64 xd = dup2(xs);
                    acc[s][0] = fma2(xd, wp.x, acc[s][0]);
                    acc[s][1] = fma2(xd, wp.y, acc[s][1]);
                }
            }
        }
        #pragma unroll
        for (int s = 0; s < 4; s++) {
            float4 o;
            unpack2(acc[s][0], o.x, o.y);
            unpack2(acc[s][1], o.z, o.w);
            if (wr[s]) *(float4*)(orw[s] + 4 * tx) = o;
        }
    }

    // ------------------------------------------------------------------
    // Segment 2: u=v=32, i=3.  cols 64..159.  thread covers v0=2*tx (pair).
    // acc2[s][i] = (out[v0*3+i], out[(v0+1)*3+i]); w pair via LDS.64.
    // ------------------------------------------------------------------
    {
        const u64* w2p = (const u64*)(sw + 4096);   // pair index: u*16 + tx
        u64 acc[4][3];
        #pragma unroll
        for (int s = 0; s < 4; s++)
            #pragma unroll
            for (int i = 0; i < 3; i++) acc[s][i] = 0ull;

        #pragma unroll 2
        for (int k = 0; k < 8; k++) {           // u = 4k .. 4k+3 -> 12 floats / row
            float4 xb[4][3];
            #pragma unroll
            for (int s = 0; s < 4; s++)
                #pragma unroll
                for (int j = 0; j < 3; j++)
                    xb[s][j] = *(const float4*)(xr[s] + 64 + 12 * k + 4 * j);
            #pragma unroll
            for (int uu = 0; uu < 4; uu++) {
                const int u = 4 * k + uu;
                u64 wp = w2p[u * 16 + tx];          // (w[u][2tx], w[u][2tx+1])
                #pragma unroll
                for (int s = 0; s < 4; s++) {
                    const float* xf = (const float*)&xb[s][0];
                    #pragma unroll
                    for (int i = 0; i < 3; i++) {
                        u64 xd = dup2(xf[uu * 3 + i]);
                        acc[s][i] = fma2(xd, wp, acc[s][i]);
                    }
                }
            }
        }
        const int c0 = 64 + 6 * tx;
        #pragma unroll
        for (int s = 0; s < 4; s++) {
            if (!wr[s]) continue;
            #pragma unroll
            for (int i = 0; i < 3; i++) {
                float lo, hi;
                unpack2(acc[s][i], lo, hi);
                orw[s][c0 + i]     = lo;   // v0
                orw[s][c0 + 3 + i] = hi;   // v0+1
            }
        }
    }

    // ------------------------------------------------------------------
    // Segment 3: u=v=16, i=5.  cols 160..239.  thread covers v = tx.
    // i-pair packing: (i0,i1),(i2,i3) f32x2 + scalar i4; dup w.
    // ------------------------------------------------------------------
    {
        const float* w3s = sw + 5120;
        u64 a01[4], a23[4];
        float a4[4];
        #pragma unroll
        for (int s = 0; s < 4; s++) { a01[s] = 0ull; a23[s] = 0ull; a4[s] = 0.0f; }

        #pragma unroll
        for (int k = 0; k < 4; k++) {           // u = 4k .. 4k+3 -> 20 floats / row
            float4 xc[4][5];
            #pragma unroll
            for (int s = 0; s < 4; s++)
                #pragma unroll
                for (int j = 0; j < 5; j++)
                    xc[s][j] = *(const float4*)(xr[s] + 160 + 20 * k + 4 * j);
            #pragma unroll
            for (int uu = 0; uu < 4; uu++) {
                const int u = 4 * k + uu;
                float wv = w3s[u * 16 + tx];
                u64 wd = dup2(wv);
                #pragma unroll
                for (int s = 0; s < 4; s++) {
                    const float* xf = (const float*)&xc[s][0];
                    const int o = uu * 5;
                    a01[s] = fma2(pack2(xf[o],     xf[o + 1]), wd, a01[s]);
                    a23[s] = fma2(pack2(xf[o + 2], xf[o + 3]), wd, a23[s]);
                    a4[s]  = fmaf(xf[o + 4], wv, a4[s]);
                }
            }
        }
        const int c0 = 160 + 5 * tx;
        #pragma unroll
        for (int s = 0; s < 4; s++) {
            if (!wr[s]) continue;
            float v0, v1, v2, v3;
            unpack2(a01[s], v0, v1);
            unpack2(a23[s], v2, v3);
            orw[s][c0]     = v0;
            orw[s][c0 + 1] = v1;
            orw[s][c0 + 2] = v2;
            orw[s][c0 + 3] = v3;
            orw[s][c0 + 4] = a4[s];
        }
    }
}

extern "C" void kernel_launch(void* const* d_in, const int* in_sizes, int n_in,
                              void* d_out, int out_size) {
    const float* x = (const float*)d_in[0];
    const float* w = (const float*)d_in[1];
    float* out = (float*)d_out;
    const int n = in_sizes[0] / 240;         // 200000
    const int blocks = (n + 31) / 32;        // 6250
    eqlin_kernel<<<blocks, 128>>>(x, w, out, n);
}

// round 2
// speedup vs baseline: 1.5169x; 1.5169x over previous
#include <cuda_runtime.h>

// Equivariant linear: segments (u,i) = (64,1),(32,3),(16,5); in==out dim 240.
// out[n, off + v*i + ii] = (1/sqrt(u)) * sum_u x[n, off + u*i + ii] * w[u][v]

typedef unsigned long long u64;

__device__ __forceinline__ u64 fma2(u64 a, u64 b, u64 c) {
    u64 d;
    asm("fma.rn.f32x2 %0, %1, %2, %3;" : "=l"(d) : "l"(a), "l"(b), "l"(c));
    return d;
}
__device__ __forceinline__ u64 dup2(float x) {
    u64 d;
    asm("mov.b64 %0, {%1, %2};" : "=l"(d) : "f"(x), "f"(x));
    return d;
}
__device__ __forceinline__ u64 pack2(float x, float y) {
    u64 d;
    asm("mov.b64 %0, {%1, %2};" : "=l"(d) : "f"(x), "f"(y));
    return d;
}
__device__ __forceinline__ void unpack2(u64 v, float& a, float& b) {
    asm("mov.b64 {%0, %1}, %2;" : "=f"(a), "=f"(b) : "l"(v));
}

#define ROW_PAD 244   // 244 mod 32 = 20 -> adjacent rows hit distinct banks

__global__ __launch_bounds__(256, 4) void eqlin_kernel(
    const float* __restrict__ x,
    const float* __restrict__ w,
    float* __restrict__ out,
    int n)
{
    extern __shared__ __align__(16) float smem[];
    float* sw = smem;                                   // 5376 floats (pre-scaled w)
    float (*sx)[ROW_PAD] = (float (*)[ROW_PAD])(smem + 5376);  // 32 x 244

    const int tid = threadIdx.x;

    // ---- stage weights, pre-scaled: seg1 *1/8, seg2 *1/sqrt(32), seg3 *1/4
    #pragma unroll
    for (int k = 0; k < 21; k++) {                      // 21*256 = 5376
        int idx = tid + k * 256;
        float s = (idx < 4096) ? 0.125f
                 : (idx < 5120) ? 0.17677669529663687f
                                : 0.25f;
        sw[idx] = w[idx] * s;
    }

    // ---- stage x tile, fully coalesced: 32 rows * 60 float4 = 1920 loads
    const long long rowbase = (long long)blockIdx.x * 32;
    #pragma unroll
    for (int k = 0; k < 8; k++) {
        int t = tid + k * 256;
        if (t < 1920) {
            int row = t / 60, c4 = t % 60;
            long long gr = rowbase + row;
            if (gr >= n) gr = n - 1;
            float4 v = *(const float4*)(x + gr * 240 + c4 * 4);
            *(float4*)&sx[row][c4 * 4] = v;
        }
    }
    __syncthreads();

    const int ty = tid >> 4;        // 0..15 -> 2 rows each
    const int tx = tid & 15;        // output-column slice
    const int r0 = ty * 2, r1 = r0 + 1;
    const long long g0 = rowbase + r0, g1 = rowbase + r1;
    const bool p0 = g0 < n, p1 = g1 < n;
    float* o0 = out + g0 * 240;
    float* o1 = out + g1 * 240;

    // ------------------------------------------------------------------
    // Segment 1: u=v=64, i=1. cols 0..63. thread covers v = 4tx..4tx+3.
    // ------------------------------------------------------------------
    {
        const ulonglong2* w1p = (const ulonglong2*)sw;  // (u*64+4tx)/4 = u*16+tx
        u64 a0l = 0, a0h = 0, a1l = 0, a1h = 0;
        #pragma unroll 4
        for (int k = 0; k < 16; k++) {
            float4 xa = *(const float4*)&sx[r0][4 * k];
            float4 xb = *(const float4*)&sx[r1][4 * k];
            #pragma unroll
            for (int uu = 0; uu < 4; uu++) {
                ulonglong2 wp = w1p[(4 * k + uu) * 16 + tx];
                float s0 = (uu == 0) ? xa.x : (uu == 1) ? xa.y : (uu == 2) ? xa.z : xa.w;
                float s1 = (uu == 0) ? xb.x : (uu == 1) ? xb.y : (uu == 2) ? xb.z : xb.w;
                u64 d0 = dup2(s0), d1 = dup2(s1);
                a0l = fma2(d0, wp.x, a0l);  a0h = fma2(d0, wp.y, a0h);
                a1l = fma2(d1, wp.x, a1l);  a1h = fma2(d1, wp.y, a1h);
            }
        }
        if (p0) { float4 o; unpack2(a0l, o.x, o.y); unpack2(a0h, o.z, o.w);
                  *(float4*)(o0 + 4 * tx) = o; }
        if (p1) { float4 o; unpack2(a1l, o.x, o.y); unpack2(a1h, o.z, o.w);
                  *(float4*)(o1 + 4 * tx) = o; }
    }

    // ------------------------------------------------------------------
    // Segment 2: u=v=32, i=3. cols 64..159. thread covers v-pair 2tx,2tx+1.
    // Process one row at a time (register relief).
    // ------------------------------------------------------------------
    #pragma unroll
    for (int r = 0; r < 2; r++) {
        const int rr = r0 + r;
        const bool pr = r ? p1 : p0;
        float* orow = r ? o1 : o0;
        const u64* w2p = (const u64*)(sw + 4096);       // pair index u*16+tx
        u64 acc[3] = {0ull, 0ull, 0ull};
        #pragma unroll 2
        for (int k = 0; k < 8; k++) {                   // u = 4k..4k+3
            float4 xb[3];
            #pragma unroll
            for (int j = 0; j < 3; j++)
                xb[j] = *(const float4*)&sx[rr][64 + 12 * k + 4 * j];
            const float* xf = (const float*)&xb[0];
            #pragma unroll
            for (int uu = 0; uu < 4; uu++) {
                u64 wp = w2p[(4 * k + uu) * 16 + tx];   // (w[u][2tx], w[u][2tx+1])
                #pragma unroll
                for (int i = 0; i < 3; i++)
                    acc[i] = fma2(dup2(xf[uu * 3 + i]), wp, acc[i]);
            }
        }
        if (pr) {
            const int c0 = 64 + 6 * tx;
            #pragma unroll
            for (int i = 0; i < 3; i++) {
                float lo, hi;
                unpack2(acc[i], lo, hi);
                orow[c0 + i]     = lo;
                orow[c0 + 3 + i] = hi;
            }
        }
    }

    // ------------------------------------------------------------------
    // Segment 3: u=v=16, i=5. cols 160..239. thread covers v = tx.
    // i-pair packing; one row at a time.
    // ------------------------------------------------------------------
    #pragma unroll
    for (int r = 0; r < 2; r++) {
        const int rr = r0 + r;
        const bool pr = r ? p1 : p0;
        float* orow = r ? o1 : o0;
        const float* w3s = sw + 5120;
        u64 a01 = 0ull, a23 = 0ull;
        float a4 = 0.0f;
        #pragma unroll
        for (int k = 0; k < 4; k++) {                   // u = 4k..4k+3
            float4 xc[5];
            #pragma unroll
            for (int j = 0; j < 5; j++)
                xc[j] = *(const float4*)&sx[rr][160 + 20 * k + 4 * j];
            const float* xf = (const float*)&xc[0];
            #pragma unroll
            for (int uu = 0; uu < 4; uu++) {
                float wv = w3s[(4 * k + uu) * 16 + tx];
                u64 wd = dup2(wv);
                const int o = uu * 5;
                a01 = fma2(pack2(xf[o],     xf[o + 1]), wd, a01);
                a23 = fma2(pack2(xf[o + 2], xf[o + 3]), wd, a23);
                a4  = fmaf(xf[o + 4], wv, a4);
            }
        }
        if (pr) {
            const int c0 = 160 + 5 * tx;
            float v0, v1, v2, v3;
            unpack2(a01, v0, v1);
            unpack2(a23, v2, v3);
            orow[c0]     = v0;
            orow[c0 + 1] = v1;
            orow[c0 + 2] = v2;
            orow[c0 + 3] = v3;
            orow[c0 + 4] = a4;
        }
    }
}

extern "C" void kernel_launch(void* const* d_in, const int* in_sizes, int n_in,
                              void* d_out, int out_size) {
    const float* x = (const float*)d_in[0];
    const float* w = (const float*)d_in[1];
    float* out = (float*)d_out;
    const int n = in_sizes[0] / 240;              // 200000
    const int blocks = (n + 31) / 32;             // 6250 (exact: 6250*32 = 200000)
    const int smem_bytes = (5376 + 32 * ROW_PAD) * 4;   // 52736
    static bool attr_set = false;
    if (!attr_set) {
        cudaFuncSetAttribute(eqlin_kernel,
                             cudaFuncAttributeMaxDynamicSharedMemorySize, smem_bytes);
        attr_set = true;
    }
    eqlin_kernel<<<blocks, 256, smem_bytes>>>(x, w, out, n);
}

// round 3
// speedup vs baseline: 2.4604x; 1.6219x over previous
#include <cuda_runtime.h>
#include <cstdint>

// Equivariant linear: segments (u,i) = (64,1),(32,3),(16,5); in==out dim 240.
// out[n, off + v*i + ii] = (1/sqrt(u)) * sum_u x[n, off + u*i + ii] * w[u][v]

typedef unsigned long long u64;

__device__ __forceinline__ u64 fma2(u64 a, u64 b, u64 c) {
    u64 d;
    asm("fma.rn.f32x2 %0, %1, %2, %3;" : "=l"(d) : "l"(a), "l"(b), "l"(c));
    return d;
}
__device__ __forceinline__ u64 dup2(float x) {
    u64 d;
    asm("mov.b64 %0, {%1, %2};" : "=l"(d) : "f"(x), "f"(x));
    return d;
}
__device__ __forceinline__ u64 pack2(float x, float y) {
    u64 d;
    asm("mov.b64 %0, {%1, %2};" : "=l"(d) : "f"(x), "f"(y));
    return d;
}
__device__ __forceinline__ void unpack2(u64 v, float& a, float& b) {
    asm("mov.b64 {%0, %1}, %2;" : "=f"(a), "=f"(b) : "l"(v));
}
__device__ __forceinline__ uint32_t s2u(const void* p) {
    uint32_t a;
    asm("{ .reg .u64 t; cvta.to.shared.u64 t, %1; cvt.u32.u64 %0, t; }"
        : "=r"(a) : "l"(p));
    return a;
}
__device__ __forceinline__ void mbar_wait0(uint32_t mbar) {
    asm volatile(
        "{\n\t.reg .pred P;\n\t"
        "W%=:\n\t"
        "mbarrier.try_wait.parity.shared.b64 P, [%0], 0;\n\t"
        "@P bra.uni D%=;\n\t"
        "bra.uni W%=;\n\t"
        "D%=:\n\t}"
        :: "r"(mbar) : "memory");
}

#define TILE_ROWS 64
#define TILE_BYTES (TILE_ROWS * 240 * 4)   // 61440, contiguous in GMEM

__global__ __launch_bounds__(256, 2) void eqlin_kernel(
    const float* __restrict__ x,
    const float* __restrict__ w,
    float* __restrict__ out,
    int n)
{
    extern __shared__ __align__(16) float smem[];
    float* sw = smem;                        // 5376 floats (pre-scaled weights)
    float* sx = smem + 5376;                 // 64 x 240 tile, NO padding (contiguous)
    const uint32_t mbar = s2u(smem + 5376 + TILE_ROWS * 240);  // 8B mbarrier

    const int tid = threadIdx.x;
    const long long rowbase = (long long)blockIdx.x * TILE_ROWS;

    // rows in this tile (grid is exact for n=200000, but stay safe)
    int tile_rows = (int)(n - rowbase);
    if (tile_rows > TILE_ROWS) tile_rows = TILE_ROWS;
    const uint32_t xfer_bytes = (uint32_t)tile_rows * 960u;

    // ---- mbarrier init, then kick the bulk x-tile load (TMA, 1 instruction)
    if (tid == 0)
        asm volatile("mbarrier.init.shared.b64 [%0], 1;" :: "r"(mbar) : "memory");
    __syncthreads();
    if (tid == 0) {
        asm volatile("mbarrier.arrive.expect_tx.shared.b64 _, [%0], %1;"
                     :: "r"(mbar), "r"(xfer_bytes) : "memory");
        asm volatile(
            "cp.async.bulk.shared::cta.global.mbarrier::complete_tx::bytes "
            "[%0], [%1], %2, [%3];"
            :: "r"(s2u(sx)), "l"(x + rowbase * 240), "r"(xfer_bytes), "r"(mbar)
            : "memory");
    }

    // ---- stage weights (overlaps the TMA flight), pre-scaled
    #pragma unroll
    for (int k = 0; k < 21; k++) {               // 21*256 = 5376
        int idx = tid + k * 256;
        float s = (idx < 4096) ? 0.125f
                 : (idx < 5120) ? 0.17677669529663687f
                                : 0.25f;
        sw[idx] = w[idx] * s;
    }
    __syncthreads();       // weights visible
    mbar_wait0(mbar);      // x tile landed

    // ---- thread mapping: 16 tx (v-slice) x 16 ty; ty owns rows ty+16s (s=0..3)
    // Interleaved rows => warp's two ty-rows are 960B apart (bank-clean, no pad).
    const int ty = tid >> 4;
    const int tx = tid & 15;
    const float* sxr[4];
    bool pr[4];
    #pragma unroll
    for (int s = 0; s < 4; s++) {
        int rr = ty + 16 * s;
        pr[s] = rr < tile_rows;
        sxr[s] = sx + rr * 240;
    }

    // ================= Segment 1: u=v=64, i=1, cols 0..63, v=4tx..4tx+3 ====
    u64 a1[4][2];
    #pragma unroll
    for (int s = 0; s < 4; s++) { a1[s][0] = 0ull; a1[s][1] = 0ull; }
    {
        const ulonglong2* w1p = (const ulonglong2*)sw;   // (u*64+4tx)/4 = u*16+tx
        #pragma unroll 4
        for (int k = 0; k < 16; k++) {
            ulonglong2 wp0 = w1p[(4 * k + 0) * 16 + tx];
            ulonglong2 wp1 = w1p[(4 * k + 1) * 16 + tx];
            ulonglong2 wp2 = w1p[(4 * k + 2) * 16 + tx];
            ulonglong2 wp3 = w1p[(4 * k + 3) * 16 + tx];
            #pragma unroll
            for (int s = 0; s < 4; s++) {
                float4 xv = *(const float4*)(sxr[s] + 4 * k);
                u64 d;
                d = dup2(xv.x); a1[s][0] = fma2(d, wp0.x, a1[s][0]); a1[s][1] = fma2(d, wp0.y, a1[s][1]);
                d = dup2(xv.y); a1[s][0] = fma2(d, wp1.x, a1[s][0]); a1[s][1] = fma2(d, wp1.y, a1[s][1]);
                d = dup2(xv.z); a1[s][0] = fma2(d, wp2.x, a1[s][0]); a1[s][1] = fma2(d, wp2.y, a1[s][1]);
                d = dup2(xv.w); a1[s][0] = fma2(d, wp3.x, a1[s][0]); a1[s][1] = fma2(d, wp3.y, a1[s][1]);
            }
        }
    }

    // ================= Segment 2: u=v=32, i=3, cols 64..159, v-pair 2tx ====
    u64 a2[4][3];
    #pragma unroll
    for (int s = 0; s < 4; s++)
        #pragma unroll
        for (int i = 0; i < 3; i++) a2[s][i] = 0ull;
    {
        const u64* w2p = (const u64*)(sw + 4096);        // pair index u*16+tx
        #pragma unroll 2
        for (int k = 0; k < 8; k++) {                    // u = 4k..4k+3
            u64 wp0 = w2p[(4 * k + 0) * 16 + tx];
            u64 wp1 = w2p[(4 * k + 1) * 16 + tx];
            u64 wp2 = w2p[(4 * k + 2) * 16 + tx];
            u64 wp3 = w2p[(4 * k + 3) * 16 + tx];
            #pragma unroll
            for (int s = 0; s < 4; s++) {
                float4 xb0 = *(const float4*)(sxr[s] + 64 + 12 * k);
                float4 xb1 = *(const float4*)(sxr[s] + 64 + 12 * k + 4);
                float4 xb2 = *(const float4*)(sxr[s] + 64 + 12 * k + 8);
                // u0: x[0..2] = xb0.xyz ; u1: xb0.w, xb1.xy ; u2: xb1.zw, xb2.x ; u3: xb2.yzw
                a2[s][0] = fma2(dup2(xb0.x), wp0, a2[s][0]);
                a2[s][1] = fma2(dup2(xb0.y), wp0, a2[s][1]);
                a2[s][2] = fma2(dup2(xb0.z), wp0, a2[s][2]);
                a2[s][0] = fma2(dup2(xb0.w), wp1, a2[s][0]);
                a2[s][1] = fma2(dup2(xb1.x), wp1, a2[s][1]);
                a2[s][2] = fma2(dup2(xb1.y), wp1, a2[s][2]);
                a2[s][0] = fma2(dup2(xb1.z), wp2, a2[s][0]);
                a2[s][1] = fma2(dup2(xb1.w), wp2, a2[s][1]);
                a2[s][2] = fma2(dup2(xb2.x), wp2, a2[s][2]);
                a2[s][0] = fma2(dup2(xb2.y), wp3, a2[s][0]);
                a2[s][1] = fma2(dup2(xb2.z), wp3, a2[s][1]);
                a2[s][2] = fma2(dup2(xb2.w), wp3, a2[s][2]);
            }
        }
    }

    // ================= Segment 3: u=v=16, i=5, cols 160..239, v=tx =========
    u64 a01[4], a23[4];
    float a4[4];
    #pragma unroll
    for (int s = 0; s < 4; s++) { a01[s] = 0ull; a23[s] = 0ull; a4[s] = 0.0f; }
    {
        const float* w3s = sw + 5120;
        #pragma unroll
        for (int k = 0; k < 4; k++) {                    // u = 4k..4k+3
            float w0 = w3s[(4 * k + 0) * 16 + tx];
            float w1 = w3s[(4 * k + 1) * 16 + tx];
            float w2 = w3s[(4 * k + 2) * 16 + tx];
            float w3 = w3s[(4 * k + 3) * 16 + tx];
            u64 d0 = dup2(w0), d1 = dup2(w1), d2 = dup2(w2), d3 = dup2(w3);
            #pragma unroll
            for (int s = 0; s < 4; s++) {
                float4 xc0 = *(const float4*)(sxr[s] + 160 + 20 * k);
                float4 xc1 = *(const float4*)(sxr[s] + 160 + 20 * k + 4);
                float4 xc2 = *(const float4*)(sxr[s] + 160 + 20 * k + 8);
                float4 xc3 = *(const float4*)(sxr[s] + 160 + 20 * k + 12);
                float4 xc4 = *(const float4*)(sxr[s] + 160 + 20 * k + 16);
                // u0: xc0.xyzw, xc1.x | u1: xc1.yzw, xc2.xy | u2: xc2.zw, xc3.xyz | u3: xc3.w, xc4.xyzw
                a01[s] = fma2(pack2(xc0.x, xc0.y), d0, a01[s]);
                a23[s] = fma2(pack2(xc0.z, xc0.w), d0, a23[s]);
                a4[s]  = fmaf(xc1.x, w0, a4[s]);
                a01[s] = fma2(pack2(xc1.y, xc1.z), d1, a01[s]);
                a23[s] = fma2(pack2(xc1.w, xc2.x), d1, a23[s]);
                a4[s]  = fmaf(xc2.y, w1, a4[s]);
                a01[s] = fma2(pack2(xc2.z, xc2.w), d2, a01[s]);
                a23[s] = fma2(pack2(xc3.x, xc3.y), d2, a23[s]);
                a4[s]  = fmaf(xc3.z, w2, a4[s]);
                a01[s] = fma2(pack2(xc3.w, xc4.x), d3, a01[s]);
                a23[s] = fma2(pack2(xc4.y, xc4.z), d3, a23[s]);
                a4[s]  = fmaf(xc4.w, w3, a4[s]);
            }
        }
    }

    // ---- all x reads done; write outputs IN-PLACE into the tile
    __syncthreads();
    #pragma unroll
    for (int s = 0; s < 4; s++) {
        if (!pr[s]) continue;
        float* orow = (float*)sxr[s];
        // seg1: cols 4tx..4tx+3
        {
            float4 o;
            unpack2(a1[s][0], o.x, o.y);
            unpack2(a1[s][1], o.z, o.w);
            *(float4*)(orow + 4 * tx) = o;
        }
        // seg2: cols 64+6tx .. +5  -> [lo0,lo1,lo2,hi0,hi1,hi2]
        {
            float lo0, lo1, lo2, hi0, hi1, hi2;
            unpack2(a2[s][0], lo0, hi0);
            unpack2(a2[s][1], lo1, hi1);
            unpack2(a2[s][2], lo2, hi2);
            float* p = orow + 64 + 6 * tx;
            *(float2*)(p)     = make_float2(lo0, lo1);
            *(float2*)(p + 2) = make_float2(lo2, hi0);
            *(float2*)(p + 4) = make_float2(hi1, hi2);
        }
        // seg3: cols 160+5tx .. +4
        {
            float v0, v1, v2, v3;
            unpack2(a01[s], v0, v1);
            unpack2(a23[s], v2, v3);
            float* p = orow + 160 + 5 * tx;
            p[0] = v0; p[1] = v1; p[2] = v2; p[3] = v3; p[4] = a4[s];
        }
    }
    __syncthreads();

    // ---- one bulk store of the contiguous tile
    if (tid == 0) {
        asm volatile("fence.proxy.async.shared::cta;" ::: "memory");
        asm volatile("cp.async.bulk.global.shared::cta.bulk_group [%0], [%1], %2;"
                     :: "l"(out + rowbase * 240), "r"(s2u(sx)), "r"(xfer_bytes)
                     : "memory");
        asm volatile("cp.async.bulk.commit_group;" ::: "memory");
        asm volatile("cp.async.bulk.wait_group 0;" ::: "memory");
    }
}

extern "C" void kernel_launch(void* const* d_in, const int* in_sizes, int n_in,
                              void* d_out, int out_size) {
    const float* x = (const float*)d_in[0];
    const float* w = (const float*)d_in[1];
    float* out = (float*)d_out;
    const int n = in_sizes[0] / 240;                     // 200000
    const int blocks = (n + TILE_ROWS - 1) / TILE_ROWS;  // 3125 (exact)
    const int smem_bytes = (5376 + TILE_ROWS * 240) * 4 + 16;  // 82960
    static bool attr_set = false;
    if (!attr_set) {
        cudaFuncSetAttribute(eqlin_kernel,
                             cudaFuncAttributeMaxDynamicSharedMemorySize, smem_bytes);
        attr_set = true;
    }
    eqlin_kernel<<<blocks, 256, smem_bytes>>>(x, w, out, n);
}